// round 16
// baseline (speedup 1.0000x reference)
#include <cuda_runtime.h>
#include <cstdint>

// Problem constants (fixed by the reference)
#define NN 50000
#define EE 800000
#define E2T 850000   // EE + NN self loops
#define DD 128
#define GG 64
#define NEG_SLOPE 0.2f
#define LN_EPS 1e-5f

// ---------------- scratch (device globals; no allocation allowed) ----------------
__device__ float g_x[NN * DD];     // final layer output (for pooling)
__device__ float g_xln[NN * DD];   // layer-normed features
__device__ float g_y[NN * DD];     // GIN pre-MLP output
__device__ float g_ssrc[NN];       // xln . att_w[D:]
__device__ float g_sdst[NN];       // xln . att_w[:D]
__device__ int   g_deg[NN];        // memset 0 -> hist counts -> alloc writes deg+1
__device__ int   g_row[NN];
__device__ int   g_cur[NN];
__device__ int   g_total;
__device__ int2  g_csr[E2T];       // {src, __float_as_int(w)}: 1 sector per edge

// smem layout for k_mlp (floats): sA[128][36] | sW[32][136] | sH[128][132]
#define SA_OFF 0
#define SW_OFF (128 * 36)
#define SH_OFF (128 * 36 + 32 * 136)
#define SMEM_FLOATS (128 * 36 + 32 * 136 + 128 * 132)
#define SMEM_BYTES (SMEM_FLOATS * 4)

// ---------------- small helpers ----------------
__device__ __forceinline__ uint32_t f2tf32(float f) {
    uint32_t r;
    asm("cvt.rna.tf32.f32 %0, %1;" : "=r"(r) : "f"(f));
    return r;
}

__device__ __forceinline__ float4 tf32x4(float4 v) {
    float4 w;
    w.x = __uint_as_float(f2tf32(v.x));
    w.y = __uint_as_float(f2tf32(v.y));
    w.z = __uint_as_float(f2tf32(v.z));
    w.w = __uint_as_float(f2tf32(v.w));
    return w;
}

__device__ __forceinline__ void mma_tf32(float* d, const uint32_t* a, const uint32_t* b) {
    asm volatile(
        "mma.sync.aligned.m16n8k8.row.col.f32.tf32.tf32.f32 "
        "{%0,%1,%2,%3}, {%4,%5,%6,%7}, {%8,%9}, {%0,%1,%2,%3};\n"
        : "+f"(d[0]), "+f"(d[1]), "+f"(d[2]), "+f"(d[3])
        : "r"(a[0]), "r"(a[1]), "r"(a[2]), "r"(a[3]), "r"(b[0]), "r"(b[1]));
}

// ---------------- fused layer-0 LN + attention scores + edge histogram ----------------
// 64-thread blocks (2 nodes): same straggler-quantization fix that won in k_agg.
// hist: warp 0 of each block covers 32 edges -> 25000 blocks * 32 = 800k exactly.
__global__ void __launch_bounds__(64)
k_lnhist(const float* __restrict__ emb, const int* __restrict__ ids,
         const float* __restrict__ gamma, const float* __restrict__ beta,
         const float* __restrict__ aw, const int* __restrict__ dst) {
    int tid = threadIdx.x;
    int node = blockIdx.x * 2 + (tid >> 5);
    int lane = tid & 31;

    // hist part: warp 0 handles 32 edges per block
    if (tid < 32) {
        int e = blockIdx.x * 32 + lane;
        if (e < EE) atomicAdd(&g_deg[dst[e]], 1);
    }

    if (node >= NN) return;

    const float* srcp = emb + (size_t)ids[node] * DD;
    float4 v = reinterpret_cast<const float4*>(srcp)[lane];

    float s = v.x + v.y + v.z + v.w;
    #pragma unroll
    for (int o = 16; o; o >>= 1) s += __shfl_xor_sync(0xffffffffu, s, o);
    float mu = s * (1.0f / 128.0f);

    float dx = v.x - mu, dy = v.y - mu, dz = v.z - mu, dw = v.w - mu;
    float q = dx * dx + dy * dy + dz * dz + dw * dw;
    #pragma unroll
    for (int o = 16; o; o >>= 1) q += __shfl_xor_sync(0xffffffffu, q, o);
    float rs = rsqrtf(q * (1.0f / 128.0f) + LN_EPS);

    float4 gm = reinterpret_cast<const float4*>(gamma)[lane];
    float4 bt = reinterpret_cast<const float4*>(beta)[lane];
    float4 xl;
    xl.x = dx * rs * gm.x + bt.x;
    xl.y = dy * rs * gm.y + bt.y;
    xl.z = dz * rs * gm.z + bt.z;
    xl.w = dw * rs * gm.w + bt.w;
    reinterpret_cast<float4*>(g_xln + (size_t)node * DD)[lane] = xl;

    float4 a0 = reinterpret_cast<const float4*>(aw)[lane];         // aw[:D]  -> dst
    float4 a1 = reinterpret_cast<const float4*>(aw + DD)[lane];    // aw[D:]  -> src
    float sd = xl.x * a0.x + xl.y * a0.y + xl.z * a0.z + xl.w * a0.w;
    float ss = xl.x * a1.x + xl.y * a1.y + xl.z * a1.z + xl.w * a1.w;
    #pragma unroll
    for (int o = 16; o; o >>= 1) {
        sd += __shfl_xor_sync(0xffffffffu, sd, o);
        ss += __shfl_xor_sync(0xffffffffu, ss, o);
    }
    if (lane == 0) { g_sdst[node] = sd; g_ssrc[node] = ss; }
}

// allocate CSR segment per node: block-level scan + ONE atomic per block.
__global__ void k_alloc() {
    __shared__ int warp_sums[8];
    __shared__ int block_base;
    int tid = threadIdx.x;
    int n = blockIdx.x * 256 + tid;
    int lane = tid & 31, wid = tid >> 5;

    int d = (n < NN) ? (g_deg[n] + 1) : 0;   // +1 self loop

    int x = d;
    #pragma unroll
    for (int o = 1; o < 32; o <<= 1) {
        int y = __shfl_up_sync(0xffffffffu, x, o);
        if (lane >= o) x += y;
    }
    if (lane == 31) warp_sums[wid] = x;
    __syncthreads();

    if (wid == 0) {
        int v = (lane < 8) ? warp_sums[lane] : 0;
        #pragma unroll
        for (int o = 1; o < 8; o <<= 1) {
            int y = __shfl_up_sync(0xffffffffu, v, o);
            if (lane >= o) v += y;
        }
        if (lane < 8) warp_sums[lane] = v;
    }
    __syncthreads();

    int block_total = warp_sums[7];
    if (tid == 0) block_base = atomicAdd(&g_total, block_total);
    __syncthreads();

    int excl = x - d + (wid ? warp_sums[wid - 1] : 0);
    int start = block_base + excl;
    if (n < NN) {
        g_deg[n] = d;                  // true degree for k_agg
        g_row[n] = start;
        g_cur[n] = start + 1;
        g_csr[start] = make_int2(n, __float_as_int(1.0f));   // self loop first
    }
}

__global__ void k_scatter(const int* __restrict__ src, const int* __restrict__ dst,
                          const float* __restrict__ ew) {
    int e = blockIdx.x * blockDim.x + threadIdx.x;
    if (e < EE) {
        int d = dst[e];
        int pos = atomicAdd(&g_cur[d], 1);
        g_csr[pos] = make_int2(src[e], __float_as_int(ew[e]));  // one 8B scattered store
    }
}

// ---------------- SINGLE-PASS attention aggregation + GIN update (warp per node) ----------------
__global__ void __launch_bounds__(64, 28)
k_agg(const float* __restrict__ eps_p, int l) {
    int warp = (blockIdx.x * blockDim.x + threadIdx.x) >> 5;
    int lane = threadIdx.x & 31;
    if (warp >= NN) return;

    int beg = g_row[warp];
    int deg = g_deg[warp];
    float sd = g_sdst[warp];

    float s_loc = 0.0f;                                 // Σ exp per lane
    float ax = 0.f, ay = 0.f, az = 0.f, aw_ = 0.f;      // single accumulator set
    const float4* xp = reinterpret_cast<const float4*>(g_xln);

    for (int base = 0; base < deg; base += 32) {
        int i = base + lane;
        int src = 0;
        float ew = 0.0f;                  // exp(sc) * w (unnormalized)
        if (i < deg) {
            int2 c = g_csr[beg + i];
            src = c.x;
            float sc = sd + g_ssrc[src];
            sc = sc >= 0.0f ? sc : NEG_SLOPE * sc;
            float ex = __expf(sc);
            s_loc += ex;
            ew = ex * __int_as_float(c.y);
        }
        int cnt = min(32, deg - base);
        int j = 0;
        #pragma unroll 2
        for (; j + 1 < cnt; j += 2) {
            int   sj0 = __shfl_sync(0xffffffffu, src, j);
            int   sj1 = __shfl_sync(0xffffffffu, src, j + 1);
            float aj0 = __shfl_sync(0xffffffffu, ew, j);
            float aj1 = __shfl_sync(0xffffffffu, ew, j + 1);
            float4 v0 = xp[(size_t)sj0 * 32 + lane];
            float4 v1 = xp[(size_t)sj1 * 32 + lane];
            ax += aj0 * v0.x; ay += aj0 * v0.y; az += aj0 * v0.z; aw_ += aj0 * v0.w;
            ax += aj1 * v1.x; ay += aj1 * v1.y; az += aj1 * v1.z; aw_ += aj1 * v1.w;
        }
        if (j < cnt) {
            int   sj = __shfl_sync(0xffffffffu, src, j);
            float aj = __shfl_sync(0xffffffffu, ew, j);
            float4 v = xp[(size_t)sj * 32 + lane];
            ax += aj * v.x; ay += aj * v.y; az += aj * v.z; aw_ += aj * v.w;
        }
    }

    // normalizer: warp-reduce Σ exp (off the gather critical path)
    #pragma unroll
    for (int o = 16; o; o >>= 1) s_loc += __shfl_xor_sync(0xffffffffu, s_loc, o);
    float inv = 1.0f / (s_loc + 1e-16f);

    float e = 1.0f + eps_p[l];
    float4 xs = xp[(size_t)warp * 32 + lane];
    float4 out;
    out.x = e * xs.x + ax * inv;
    out.y = e * xs.y + ay * inv;
    out.z = e * xs.z + az * inv;
    out.w = e * xs.w + aw_ * inv;
    reinterpret_cast<float4*>(g_y + (size_t)warp * DD)[lane] = out;
}

// ---------------- fused MLP with register double-buffered global loads (R11 shape) ----------------
__global__ void __launch_bounds__(256)
k_mlp(const float* __restrict__ W1, const float* __restrict__ B1,
      const float* __restrict__ W2, const float* __restrict__ B2,
      int M, int do_ln,
      const float* __restrict__ gamma, const float* __restrict__ beta,
      const float* __restrict__ aw) {
    extern __shared__ float smem[];
    float* sA = smem + SA_OFF;   // [128][36]
    float* sW = smem + SW_OFF;   // [32][136]
    float* sH = smem + SH_OFF;   // [128][132]

    int tid = threadIdx.x;
    int m0 = blockIdx.x * 128;
    int wid = tid >> 5, lane = tid & 31;
    int wm = (wid >> 2) * 64, wn = (wid & 3) * 32;
    int gq = lane >> 2, tq = lane & 3;

    int ra = tid >> 3,  ca = tid & 7;     // A tile: row, col4
    int rw = tid >> 5,  cw = tid & 31;    // W tile: row, col4

    float acc[4][4][4];
    #pragma unroll
    for (int a = 0; a < 4; a++)
        #pragma unroll
        for (int b = 0; b < 4; b++)
            #pragma unroll
            for (int c = 0; c < 4; c++) acc[a][b][c] = 0.0f;

    float4 pa[4], pw[4];

    // prologue: load chunk 0 (A from g_y, W1 chunk 0)
    #pragma unroll
    for (int it = 0; it < 4; it++) {
        int r = ra + it * 32;
        int gr = m0 + r;
        pa[it] = (gr < M) ? reinterpret_cast<const float4*>(g_y + (size_t)gr * 128)[ca]
                          : make_float4(0.f, 0.f, 0.f, 0.f);
        pw[it] = reinterpret_cast<const float4*>(W1 + (size_t)(it * 8 + rw) * 128)[cw];
    }

    // ---- Phase A: H = relu(A @ W1 + b1) ----
    for (int kc = 0; kc < 4; kc++) {
        __syncthreads();
        #pragma unroll
        for (int it = 0; it < 4; it++) {
            int r = ra + it * 32;
            *reinterpret_cast<float4*>(&sA[r * 36 + ca * 4]) = tf32x4(pa[it]);
            *reinterpret_cast<float4*>(&sW[(it * 8 + rw) * 136 + cw * 4]) = tf32x4(pw[it]);
        }
        __syncthreads();

        if (kc < 3) {
            #pragma unroll
            for (int it = 0; it < 4; it++) {
                int r = ra + it * 32;
                int gr = m0 + r;
                pa[it] = (gr < M)
                    ? reinterpret_cast<const float4*>(g_y + (size_t)gr * 128 + (kc + 1) * 32)[ca]
                    : make_float4(0.f, 0.f, 0.f, 0.f);
                pw[it] = reinterpret_cast<const float4*>(
                             W1 + (size_t)((kc + 1) * 32 + it * 8 + rw) * 128)[cw];
            }
        }

        #pragma unroll
        for (int ks = 0; ks < 4; ks++) {
            int k0 = ks * 8;
            uint32_t afr[4][4];
            #pragma unroll
            for (int mt = 0; mt < 4; mt++) {
                int r = wm + mt * 16;
                afr[mt][0] = __float_as_uint(sA[(r + gq) * 36 + k0 + tq]);
                afr[mt][1] = __float_as_uint(sA[(r + gq + 8) * 36 + k0 + tq]);
                afr[mt][2] = __float_as_uint(sA[(r + gq) * 36 + k0 + tq + 4]);
                afr[mt][3] = __float_as_uint(sA[(r + gq + 8) * 36 + k0 + tq + 4]);
            }
            uint32_t bfr[4][2];
            #pragma unroll
            for (int nt = 0; nt < 4; nt++) {
                int c = wn + nt * 8 + gq;
                bfr[nt][0] = __float_as_uint(sW[(k0 + tq) * 136 + c]);
                bfr[nt][1] = __float_as_uint(sW[(k0 + tq + 4) * 136 + c]);
            }
            #pragma unroll
            for (int mt = 0; mt < 4; mt++)
                #pragma unroll
                for (int nt = 0; nt < 4; nt++)
                    mma_tf32(acc[mt][nt], afr[mt], bfr[nt]);
        }
    }

    // prologue for phase B: load W2 chunk 0 while epilogue A runs
    #pragma unroll
    for (int it = 0; it < 4; it++)
        pw[it] = reinterpret_cast<const float4*>(W2 + (size_t)(it * 8 + rw) * 128)[cw];

    // epilogue A: bias + relu -> sH (tf32-converted for phase B mma)
    __syncthreads();
    #pragma unroll
    for (int mt = 0; mt < 4; mt++) {
        #pragma unroll
        for (int nt = 0; nt < 4; nt++) {
            int row = wm + mt * 16 + gq;
            int col = wn + nt * 8 + 2 * tq;
            float b0 = B1[col], b1 = B1[col + 1];
            float v0 = fmaxf(acc[mt][nt][0] + b0, 0.0f);
            float v1 = fmaxf(acc[mt][nt][1] + b1, 0.0f);
            float v2 = fmaxf(acc[mt][nt][2] + b0, 0.0f);
            float v3 = fmaxf(acc[mt][nt][3] + b1, 0.0f);
            sH[row * 132 + col]       = __uint_as_float(f2tf32(v0));
            sH[row * 132 + col + 1]   = __uint_as_float(f2tf32(v1));
            sH[(row + 8) * 132 + col]     = __uint_as_float(f2tf32(v2));
            sH[(row + 8) * 132 + col + 1] = __uint_as_float(f2tf32(v3));
            acc[mt][nt][0] = 0.0f; acc[mt][nt][1] = 0.0f;
            acc[mt][nt][2] = 0.0f; acc[mt][nt][3] = 0.0f;
        }
    }

    // ---- Phase B: Out = relu(H @ W2 + b2) ----
    for (int kc = 0; kc < 4; kc++) {
        __syncthreads();
        #pragma unroll
        for (int it = 0; it < 4; it++)
            *reinterpret_cast<float4*>(&sW[(it * 8 + rw) * 136 + cw * 4]) = tf32x4(pw[it]);
        __syncthreads();

        if (kc < 3) {
            #pragma unroll
            for (int it = 0; it < 4; it++)
                pw[it] = reinterpret_cast<const float4*>(
                             W2 + (size_t)((kc + 1) * 32 + it * 8 + rw) * 128)[cw];
        }

        #pragma unroll
        for (int ks = 0; ks < 4; ks++) {
            int k0 = kc * 32 + ks * 8;
            int k0s = ks * 8;
            uint32_t afr[4][4];
            #pragma unroll
            for (int mt = 0; mt < 4; mt++) {
                int r = wm + mt * 16;
                afr[mt][0] = __float_as_uint(sH[(r + gq) * 132 + k0 + tq]);
                afr[mt][1] = __float_as_uint(sH[(r + gq + 8) * 132 + k0 + tq]);
                afr[mt][2] = __float_as_uint(sH[(r + gq) * 132 + k0 + tq + 4]);
                afr[mt][3] = __float_as_uint(sH[(r + gq + 8) * 132 + k0 + tq + 4]);
            }
            uint32_t bfr[4][2];
            #pragma unroll
            for (int nt = 0; nt < 4; nt++) {
                int c = wn + nt * 8 + gq;
                bfr[nt][0] = __float_as_uint(sW[(k0s + tq) * 136 + c]);
                bfr[nt][1] = __float_as_uint(sW[(k0s + tq + 4) * 136 + c]);
            }
            #pragma unroll
            for (int mt = 0; mt < 4; mt++)
                #pragma unroll
                for (int nt = 0; nt < 4; nt++)
                    mma_tf32(acc[mt][nt], afr[mt], bfr[nt]);
        }
    }

    if (!do_ln) {
        #pragma unroll
        for (int mt = 0; mt < 4; mt++) {
            #pragma unroll
            for (int nt = 0; nt < 4; nt++) {
                int row = m0 + wm + mt * 16 + gq;
                int col = wn + nt * 8 + 2 * tq;
                float b0 = B2[col], b1 = B2[col + 1];
                float v0 = fmaxf(acc[mt][nt][0] + b0, 0.0f);
                float v1 = fmaxf(acc[mt][nt][1] + b1, 0.0f);
                float v2 = fmaxf(acc[mt][nt][2] + b0, 0.0f);
                float v3 = fmaxf(acc[mt][nt][3] + b1, 0.0f);
                if (row < M)
                    *reinterpret_cast<float2*>(g_x + (size_t)row * 128 + col) = make_float2(v0, v1);
                if (row + 8 < M)
                    *reinterpret_cast<float2*>(g_x + (size_t)(row + 8) * 128 + col) = make_float2(v2, v3);
            }
        }
        return;
    }

    // epilogue B (fused LN path): stage relu'd out in sH, then warp-per-row LN + scores
    __syncthreads();
    #pragma unroll
    for (int mt = 0; mt < 4; mt++) {
        #pragma unroll
        for (int nt = 0; nt < 4; nt++) {
            int row = wm + mt * 16 + gq;
            int col = wn + nt * 8 + 2 * tq;
            float b0 = B2[col], b1 = B2[col + 1];
            sH[row * 132 + col]           = fmaxf(acc[mt][nt][0] + b0, 0.0f);
            sH[row * 132 + col + 1]       = fmaxf(acc[mt][nt][1] + b1, 0.0f);
            sH[(row + 8) * 132 + col]     = fmaxf(acc[mt][nt][2] + b0, 0.0f);
            sH[(row + 8) * 132 + col + 1] = fmaxf(acc[mt][nt][3] + b1, 0.0f);
        }
    }
    __syncthreads();

    float4 gm = reinterpret_cast<const float4*>(gamma)[lane];
    float4 bt = reinterpret_cast<const float4*>(beta)[lane];
    float4 aw0 = reinterpret_cast<const float4*>(aw)[lane];
    float4 aw1 = reinterpret_cast<const float4*>(aw + DD)[lane];

    for (int r = wid * 16; r < wid * 16 + 16; r++) {
        int gr = m0 + r;
        if (gr >= M) break;
        float4 v = *reinterpret_cast<float4*>(&sH[r * 132 + lane * 4]);

        float s = v.x + v.y + v.z + v.w;
        #pragma unroll
        for (int o = 16; o; o >>= 1) s += __shfl_xor_sync(0xffffffffu, s, o);
        float mu = s * (1.0f / 128.0f);

        float dx = v.x - mu, dy = v.y - mu, dz = v.z - mu, dw = v.w - mu;
        float q = dx * dx + dy * dy + dz * dz + dw * dw;
        #pragma unroll
        for (int o = 16; o; o >>= 1) q += __shfl_xor_sync(0xffffffffu, q, o);
        float rs = rsqrtf(q * (1.0f / 128.0f) + LN_EPS);

        float4 xl;
        xl.x = dx * rs * gm.x + bt.x;
        xl.y = dy * rs * gm.y + bt.y;
        xl.z = dz * rs * gm.z + bt.z;
        xl.w = dw * rs * gm.w + bt.w;
        reinterpret_cast<float4*>(g_xln + (size_t)gr * DD)[lane] = xl;

        float sd = xl.x * aw0.x + xl.y * aw0.y + xl.z * aw0.z + xl.w * aw0.w;
        float ss = xl.x * aw1.x + xl.y * aw1.y + xl.z * aw1.z + xl.w * aw1.w;
        #pragma unroll
        for (int o = 16; o; o >>= 1) {
            sd += __shfl_xor_sync(0xffffffffu, sd, o);
            ss += __shfl_xor_sync(0xffffffffu, ss, o);
        }
        if (lane == 0) { g_sdst[gr] = sd; g_ssrc[gr] = ss; }
    }
}

// ---------------- fused pool + head: one block per graph, binary search boundaries ----------------
__global__ void k_poolhead(const int* __restrict__ batch,
                           const float* __restrict__ wh1, const float* __restrict__ bh1,
                           const float* __restrict__ wh2, const float* __restrict__ bh2,
                           float* __restrict__ out) {
    __shared__ float sg[128];
    __shared__ float sh[64];
    int g = blockIdx.x;
    int t = threadIdx.x;   // 128 threads = 128 dims

    // lower_bound(g) and lower_bound(g+1) on sorted batch
    int a = 0, b = NN;
    while (a < b) { int m = (a + b) >> 1; if (batch[m] < g) a = m + 1; else b = m; }
    int lo = a;
    b = NN;
    while (a < b) { int m = (a + b) >> 1; if (batch[m] < g + 1) a = m + 1; else b = m; }
    int hi = a;

    // segmented reduction with 4 partial sums for MLP
    float acc0 = 0.f, acc1 = 0.f, acc2 = 0.f, acc3 = 0.f;
    int n = lo;
    for (; n + 3 < hi; n += 4) {
        acc0 += g_x[(size_t)n * DD + t];
        acc1 += g_x[(size_t)(n + 1) * DD + t];
        acc2 += g_x[(size_t)(n + 2) * DD + t];
        acc3 += g_x[(size_t)(n + 3) * DD + t];
    }
    for (; n < hi; n++) acc0 += g_x[(size_t)n * DD + t];

    float cnt = fmaxf((float)(hi - lo), 1.0f);
    sg[t] = ((acc0 + acc1) + (acc2 + acc3)) / cnt;
    __syncthreads();

    if (t < 64) {
        float h = bh1[t];
        #pragma unroll 8
        for (int k = 0; k < 128; k++) h += sg[k] * wh1[k * 64 + t];
        sh[t] = fmaxf(h, 0.0f);
    }
    __syncthreads();
    if (t < 2) {
        float o = bh2[t];
        for (int k = 0; k < 64; k++) o += sh[k] * wh2[k * 2 + t];
        out[g * 2 + t] = o;
    }
}

// ---------------- launch ----------------
extern "C" void kernel_launch(void* const* d_in, const int* in_sizes, int n_in,
                              void* d_out, int out_size) {
    const int*   node_ids = (const int*)d_in[0];
    const int*   edge_idx = (const int*)d_in[1];   // [2, E]
    const float* edge_w   = (const float*)d_in[2];
    const int*   batch    = (const int*)d_in[3];
    const float* emb      = (const float*)d_in[4];
    const float* ln_g     = (const float*)d_in[5];
    const float* ln_b     = (const float*)d_in[6];
    const float* att_w    = (const float*)d_in[7];
    const float* w1       = (const float*)d_in[8];
    const float* b1       = (const float*)d_in[9];
    const float* w2       = (const float*)d_in[10];
    const float* b2       = (const float*)d_in[11];
    const float* epsp     = (const float*)d_in[12];
    const float* wh1      = (const float*)d_in[13];
    const float* bh1      = (const float*)d_in[14];
    const float* wh2      = (const float*)d_in[15];
    const float* bh2      = (const float*)d_in[16];
    float* out = (float*)d_out;

    const int* srcp = edge_idx;
    const int* dstp = edge_idx + EE;

    cudaFuncSetAttribute(k_mlp, cudaFuncAttributeMaxDynamicSharedMemorySize, SMEM_BYTES);

    // zero scratch via memset nodes (not kernel launches)
    void *p_deg, *p_total;
    cudaGetSymbolAddress(&p_deg, g_deg);
    cudaGetSymbolAddress(&p_total, g_total);
    cudaMemsetAsync(p_deg, 0, NN * sizeof(int));
    cudaMemsetAsync(p_total, 0, sizeof(int));

    int small_blocks = NN / 2;               // 25000 (lnhist & agg: 2 warps per block)
    int mlp_blocks   = (NN + 127) / 128;     // 391

    // launch #0: fused layer-0 LN + hist (64-thread blocks)
    k_lnhist<<<small_blocks, 64>>>(emb, node_ids, ln_g, ln_b, att_w, dstp);
    // #1, #2: CSR build
    k_alloc<<<196, 256>>>();
    k_scatter<<<(EE + 255) / 256, 256>>>(srcp, dstp, edge_w);
    // #3: k_agg layer 0  <- lands in the ncu capture slot
    k_agg<<<small_blocks, 64>>>(epsp, 0);
    k_mlp<<<mlp_blocks, 256, SMEM_BYTES>>>(w1, b1, w2, b2, NN, /*do_ln=*/1,
                                           ln_g + DD, ln_b + DD, att_w + 2 * DD);
    // layer 1
    k_agg<<<small_blocks, 64>>>(epsp, 1);
    k_mlp<<<mlp_blocks, 256, SMEM_BYTES>>>(w1 + DD * DD, b1 + DD, w2 + DD * DD, b2 + DD, NN,
                                           /*do_ln=*/0, nullptr, nullptr, nullptr);

    k_poolhead<<<GG, 128>>>(batch, wh1, bh1, wh2, bh2, out);
}

// round 17
// speedup vs baseline: 1.0572x; 1.0572x over previous
#include <cuda_runtime.h>
#include <cuda_fp16.h>
#include <cstdint>

// Problem constants (fixed by the reference)
#define NN 50000
#define EE 800000
#define E2T 850000   // EE + NN self loops
#define DD 128
#define GG 64
#define NEG_SLOPE 0.2f
#define LN_EPS 1e-5f

// ---------------- scratch (device globals; no allocation allowed) ----------------
__device__ float g_x[NN * DD];     // final layer output (for pooling)
__device__ float g_xln[NN * DD];   // layer-normed features
__device__ float g_y[NN * DD];     // GIN pre-MLP output
__device__ float g_ssrc[NN];       // xln . att_w[D:]
__device__ float g_sdst[NN];       // xln . att_w[:D]
__device__ int   g_deg[NN];        // memset 0 -> hist counts -> alloc writes deg+1
__device__ int   g_row[NN];
__device__ int   g_cur[NN];
__device__ int   g_total;
__device__ int2  g_csr[E2T];       // {src, __float_as_int(w)}: 1 sector per edge

// k_mlp smem (32-bit words): sA/sH region [128][68] | sW region [64][136]
// float staging for LN epilogue overlays the whole blob: [128][132] floats
#define RA_PAD 68          // words per A/H row (64 half2 data + 4 pad): banks 4*gq+tq distinct
#define RW_PAD 136         // words per W k2-row (128 half2 data + 8 pad): banks 8*tq+gq distinct
#define SW_OFF 8704        // 128*68
#define SMEM_WORDS (8704 + 64 * 136)   // 17408 words = 69632 B
#define SMEM_BYTES (SMEM_WORDS * 4)

// ---------------- small helpers ----------------
__device__ __forceinline__ uint32_t packh2(float a, float b) {
    __half2 h = __floats2half2_rn(a, b);
    return *reinterpret_cast<uint32_t*>(&h);
}

__device__ __forceinline__ void mma_f16(float* d, const uint32_t* a, const uint32_t* b) {
    asm volatile(
        "mma.sync.aligned.m16n8k16.row.col.f32.f16.f16.f32 "
        "{%0,%1,%2,%3}, {%4,%5,%6,%7}, {%8,%9}, {%0,%1,%2,%3};\n"
        : "+f"(d[0]), "+f"(d[1]), "+f"(d[2]), "+f"(d[3])
        : "r"(a[0]), "r"(a[1]), "r"(a[2]), "r"(a[3]), "r"(b[0]), "r"(b[1]));
}

// ---------------- fused layer-0 LN + attention scores + edge histogram ----------------
__global__ void __launch_bounds__(64)
k_lnhist(const float* __restrict__ emb, const int* __restrict__ ids,
         const float* __restrict__ gamma, const float* __restrict__ beta,
         const float* __restrict__ aw, const int* __restrict__ dst) {
    int tid = threadIdx.x;
    int node = blockIdx.x * 2 + (tid >> 5);
    int lane = tid & 31;

    if (tid < 32) {
        int e = blockIdx.x * 32 + lane;
        if (e < EE) atomicAdd(&g_deg[dst[e]], 1);
    }

    if (node >= NN) return;

    const float* srcp = emb + (size_t)ids[node] * DD;
    float4 v = reinterpret_cast<const float4*>(srcp)[lane];

    float s = v.x + v.y + v.z + v.w;
    #pragma unroll
    for (int o = 16; o; o >>= 1) s += __shfl_xor_sync(0xffffffffu, s, o);
    float mu = s * (1.0f / 128.0f);

    float dx = v.x - mu, dy = v.y - mu, dz = v.z - mu, dw = v.w - mu;
    float q = dx * dx + dy * dy + dz * dz + dw * dw;
    #pragma unroll
    for (int o = 16; o; o >>= 1) q += __shfl_xor_sync(0xffffffffu, q, o);
    float rs = rsqrtf(q * (1.0f / 128.0f) + LN_EPS);

    float4 gm = reinterpret_cast<const float4*>(gamma)[lane];
    float4 bt = reinterpret_cast<const float4*>(beta)[lane];
    float4 xl;
    xl.x = dx * rs * gm.x + bt.x;
    xl.y = dy * rs * gm.y + bt.y;
    xl.z = dz * rs * gm.z + bt.z;
    xl.w = dw * rs * gm.w + bt.w;
    reinterpret_cast<float4*>(g_xln + (size_t)node * DD)[lane] = xl;

    float4 a0 = reinterpret_cast<const float4*>(aw)[lane];
    float4 a1 = reinterpret_cast<const float4*>(aw + DD)[lane];
    float sd = xl.x * a0.x + xl.y * a0.y + xl.z * a0.z + xl.w * a0.w;
    float ss = xl.x * a1.x + xl.y * a1.y + xl.z * a1.z + xl.w * a1.w;
    #pragma unroll
    for (int o = 16; o; o >>= 1) {
        sd += __shfl_xor_sync(0xffffffffu, sd, o);
        ss += __shfl_xor_sync(0xffffffffu, ss, o);
    }
    if (lane == 0) { g_sdst[node] = sd; g_ssrc[node] = ss; }
}

// allocate CSR segment per node: block-level scan + ONE atomic per block.
__global__ void k_alloc() {
    __shared__ int warp_sums[8];
    __shared__ int block_base;
    int tid = threadIdx.x;
    int n = blockIdx.x * 256 + tid;
    int lane = tid & 31, wid = tid >> 5;

    int d = (n < NN) ? (g_deg[n] + 1) : 0;   // +1 self loop

    int x = d;
    #pragma unroll
    for (int o = 1; o < 32; o <<= 1) {
        int y = __shfl_up_sync(0xffffffffu, x, o);
        if (lane >= o) x += y;
    }
    if (lane == 31) warp_sums[wid] = x;
    __syncthreads();

    if (wid == 0) {
        int v = (lane < 8) ? warp_sums[lane] : 0;
        #pragma unroll
        for (int o = 1; o < 8; o <<= 1) {
            int y = __shfl_up_sync(0xffffffffu, v, o);
            if (lane >= o) v += y;
        }
        if (lane < 8) warp_sums[lane] = v;
    }
    __syncthreads();

    int block_total = warp_sums[7];
    if (tid == 0) block_base = atomicAdd(&g_total, block_total);
    __syncthreads();

    int excl = x - d + (wid ? warp_sums[wid - 1] : 0);
    int start = block_base + excl;
    if (n < NN) {
        g_deg[n] = d;
        g_row[n] = start;
        g_cur[n] = start + 1;
        g_csr[start] = make_int2(n, __float_as_int(1.0f));   // self loop first
    }
}

__global__ void k_scatter(const int* __restrict__ src, const int* __restrict__ dst,
                          const float* __restrict__ ew) {
    int e = blockIdx.x * blockDim.x + threadIdx.x;
    if (e < EE) {
        int d = dst[e];
        int pos = atomicAdd(&g_cur[d], 1);
        g_csr[pos] = make_int2(src[e], __float_as_int(ew[e]));
    }
}

// ---------------- SINGLE-PASS attention aggregation + GIN update (warp per node) ----------------
__global__ void __launch_bounds__(64, 28)
k_agg(const float* __restrict__ eps_p, int l) {
    int warp = (blockIdx.x * blockDim.x + threadIdx.x) >> 5;
    int lane = threadIdx.x & 31;
    if (warp >= NN) return;

    int beg = g_row[warp];
    int deg = g_deg[warp];
    float sd = g_sdst[warp];

    float s_loc = 0.0f;
    float ax = 0.f, ay = 0.f, az = 0.f, aw_ = 0.f;
    const float4* xp = reinterpret_cast<const float4*>(g_xln);

    for (int base = 0; base < deg; base += 32) {
        int i = base + lane;
        int src = 0;
        float ew = 0.0f;
        if (i < deg) {
            int2 c = g_csr[beg + i];
            src = c.x;
            float sc = sd + g_ssrc[src];
            sc = sc >= 0.0f ? sc : NEG_SLOPE * sc;
            float ex = __expf(sc);
            s_loc += ex;
            ew = ex * __int_as_float(c.y);
        }
        int cnt = min(32, deg - base);
        int j = 0;
        #pragma unroll 2
        for (; j + 1 < cnt; j += 2) {
            int   sj0 = __shfl_sync(0xffffffffu, src, j);
            int   sj1 = __shfl_sync(0xffffffffu, src, j + 1);
            float aj0 = __shfl_sync(0xffffffffu, ew, j);
            float aj1 = __shfl_sync(0xffffffffu, ew, j + 1);
            float4 v0 = xp[(size_t)sj0 * 32 + lane];
            float4 v1 = xp[(size_t)sj1 * 32 + lane];
            ax += aj0 * v0.x; ay += aj0 * v0.y; az += aj0 * v0.z; aw_ += aj0 * v0.w;
            ax += aj1 * v1.x; ay += aj1 * v1.y; az += aj1 * v1.z; aw_ += aj1 * v1.w;
        }
        if (j < cnt) {
            int   sj = __shfl_sync(0xffffffffu, src, j);
            float aj = __shfl_sync(0xffffffffu, ew, j);
            float4 v = xp[(size_t)sj * 32 + lane];
            ax += aj * v.x; ay += aj * v.y; az += aj * v.z; aw_ += aj * v.w;
        }
    }

    #pragma unroll
    for (int o = 16; o; o >>= 1) s_loc += __shfl_xor_sync(0xffffffffu, s_loc, o);
    float inv = 1.0f / (s_loc + 1e-16f);

    float e = 1.0f + eps_p[l];
    float4 xs = xp[(size_t)warp * 32 + lane];
    float4 out;
    out.x = e * xs.x + ax * inv;
    out.y = e * xs.y + ay * inv;
    out.z = e * xs.z + az * inv;
    out.w = e * xs.w + aw_ * inv;
    reinterpret_cast<float4*>(g_y + (size_t)warp * DD)[lane] = out;
}

// ---------------- fused MLP: fp16 mma (m16n8k16, 2x the tf32 rate), full-K tiles ----------------
// A/H packed half2 along k: sA[row][k2], RA_PAD=68 words/row.
// W packed half2 along k: sW[k2][n], RW_PAD=136 words/k2-row.
__global__ void __launch_bounds__(256)
k_mlp(const float* __restrict__ W1, const float* __restrict__ B1,
      const float* __restrict__ W2, const float* __restrict__ B2,
      int M, int do_ln,
      const float* __restrict__ gamma, const float* __restrict__ beta,
      const float* __restrict__ aw) {
    extern __shared__ uint32_t smem_u[];
    uint32_t* sA = smem_u;              // [128][68]   (A in phase A, H in phase B)
    uint32_t* sW = smem_u + SW_OFF;     // [64][136]
    float* sFin  = reinterpret_cast<float*>(smem_u);  // [128][132] LN staging (overlays all)

    int tid = threadIdx.x;
    int m0 = blockIdx.x * 128;
    int wid = tid >> 5, lane = tid & 31;
    int wm = (wid >> 2) * 64, wn = (wid & 3) * 32;
    int gq = lane >> 2, tq = lane & 3;

    float acc[4][4][4];
    #pragma unroll
    for (int a = 0; a < 4; a++)
        #pragma unroll
        for (int b = 0; b < 4; b++)
            #pragma unroll
            for (int c = 0; c < 4; c++) acc[a][b][c] = 0.0f;

    // ---- load A (full 128x128 from g_y) -> sA, half2-packed along k ----
    #pragma unroll
    for (int it = 0; it < 16; it++) {
        int idx = tid + it * 256;        // 0..4095
        int r = idx >> 5, c = idx & 31;  // row, float4 index (k = 4c)
        int gr = m0 + r;
        float4 v = (gr < M)
            ? reinterpret_cast<const float4*>(g_y + (size_t)gr * 128)[c]
            : make_float4(0.f, 0.f, 0.f, 0.f);
        uint32_t* p = sA + r * RA_PAD + c * 2;
        p[0] = packh2(v.x, v.y);
        p[1] = packh2(v.z, v.w);
    }
    // ---- load W1 (full) -> sW: sW[k2][n] = {W[2k2][n], W[2k2+1][n]} ----
    #pragma unroll
    for (int it = 0; it < 8; it++) {
        int idx = tid + it * 256;        // 0..2047
        int k2 = idx >> 5, c = idx & 31; // k2-row, 4-n group
        float4 va = reinterpret_cast<const float4*>(W1 + (size_t)(2 * k2) * 128)[c];
        float4 vb = reinterpret_cast<const float4*>(W1 + (size_t)(2 * k2 + 1) * 128)[c];
        uint32_t* p = sW + k2 * RW_PAD + c * 4;
        p[0] = packh2(va.x, vb.x);
        p[1] = packh2(va.y, vb.y);
        p[2] = packh2(va.z, vb.z);
        p[3] = packh2(va.w, vb.w);
    }
    __syncthreads();

    // ---- Phase A mma: 8 k16-steps ----
    #pragma unroll
    for (int ks = 0; ks < 8; ks++) {
        int k2b = ks * 8;
        uint32_t afr[4][4];
        #pragma unroll
        for (int mt = 0; mt < 4; mt++) {
            int r = wm + mt * 16;
            afr[mt][0] = sA[(r + gq) * RA_PAD + k2b + tq];
            afr[mt][1] = sA[(r + gq + 8) * RA_PAD + k2b + tq];
            afr[mt][2] = sA[(r + gq) * RA_PAD + k2b + 4 + tq];
            afr[mt][3] = sA[(r + gq + 8) * RA_PAD + k2b + 4 + tq];
        }
        uint32_t bfr[4][2];
        #pragma unroll
        for (int nt = 0; nt < 4; nt++) {
            int c = wn + nt * 8 + gq;
            bfr[nt][0] = sW[(k2b + tq) * RW_PAD + c];
            bfr[nt][1] = sW[(k2b + 4 + tq) * RW_PAD + c];
        }
        #pragma unroll
        for (int mt = 0; mt < 4; mt++)
            #pragma unroll
            for (int nt = 0; nt < 4; nt++)
                mma_f16(acc[mt][nt], afr[mt], bfr[nt]);
    }
    __syncthreads();   // all warps done reading sA (A) and sW (W1)

    // ---- epilogue A: H = relu(acc + b1) -> sA (half2 packed along k=col) ----
    #pragma unroll
    for (int mt = 0; mt < 4; mt++) {
        #pragma unroll
        for (int nt = 0; nt < 4; nt++) {
            int row = wm + mt * 16 + gq;
            int colw = ((wn + nt * 8) >> 1) + tq;     // half2 word index of col pair
            int col = wn + nt * 8 + 2 * tq;
            float b0 = B1[col], b1 = B1[col + 1];
            float v0 = fmaxf(acc[mt][nt][0] + b0, 0.0f);
            float v1 = fmaxf(acc[mt][nt][1] + b1, 0.0f);
            float v2 = fmaxf(acc[mt][nt][2] + b0, 0.0f);
            float v3 = fmaxf(acc[mt][nt][3] + b1, 0.0f);
            sA[row * RA_PAD + colw]       = packh2(v0, v1);
            sA[(row + 8) * RA_PAD + colw] = packh2(v2, v3);
            acc[mt][nt][0] = 0.0f; acc[mt][nt][1] = 0.0f;
            acc[mt][nt][2] = 0.0f; acc[mt][nt][3] = 0.0f;
        }
    }
    // ---- load W2 (full) -> sW ----
    #pragma unroll
    for (int it = 0; it < 8; it++) {
        int idx = tid + it * 256;
        int k2 = idx >> 5, c = idx & 31;
        float4 va = reinterpret_cast<const float4*>(W2 + (size_t)(2 * k2) * 128)[c];
        float4 vb = reinterpret_cast<const float4*>(W2 + (size_t)(2 * k2 + 1) * 128)[c];
        uint32_t* p = sW + k2 * RW_PAD + c * 4;
        p[0] = packh2(va.x, vb.x);
        p[1] = packh2(va.y, vb.y);
        p[2] = packh2(va.z, vb.z);
        p[3] = packh2(va.w, vb.w);
    }
    __syncthreads();

    // ---- Phase B mma: Out = H @ W2 ----
    #pragma unroll
    for (int ks = 0; ks < 8; ks++) {
        int k2b = ks * 8;
        uint32_t afr[4][4];
        #pragma unroll
        for (int mt = 0; mt < 4; mt++) {
            int r = wm + mt * 16;
            afr[mt][0] = sA[(r + gq) * RA_PAD + k2b + tq];
            afr[mt][1] = sA[(r + gq + 8) * RA_PAD + k2b + tq];
            afr[mt][2] = sA[(r + gq) * RA_PAD + k2b + 4 + tq];
            afr[mt][3] = sA[(r + gq + 8) * RA_PAD + k2b + 4 + tq];
        }
        uint32_t bfr[4][2];
        #pragma unroll
        for (int nt = 0; nt < 4; nt++) {
            int c = wn + nt * 8 + gq;
            bfr[nt][0] = sW[(k2b + tq) * RW_PAD + c];
            bfr[nt][1] = sW[(k2b + 4 + tq) * RW_PAD + c];
        }
        #pragma unroll
        for (int mt = 0; mt < 4; mt++)
            #pragma unroll
            for (int nt = 0; nt < 4; nt++)
                mma_f16(acc[mt][nt], afr[mt], bfr[nt]);
    }

    if (!do_ln) {
        // epilogue B: bias + relu -> g_x directly
        #pragma unroll
        for (int mt = 0; mt < 4; mt++) {
            #pragma unroll
            for (int nt = 0; nt < 4; nt++) {
                int row = m0 + wm + mt * 16 + gq;
                int col = wn + nt * 8 + 2 * tq;
                float b0 = B2[col], b1 = B2[col + 1];
                float v0 = fmaxf(acc[mt][nt][0] + b0, 0.0f);
                float v1 = fmaxf(acc[mt][nt][1] + b1, 0.0f);
                float v2 = fmaxf(acc[mt][nt][2] + b0, 0.0f);
                float v3 = fmaxf(acc[mt][nt][3] + b1, 0.0f);
                if (row < M)
                    *reinterpret_cast<float2*>(g_x + (size_t)row * 128 + col) = make_float2(v0, v1);
                if (row + 8 < M)
                    *reinterpret_cast<float2*>(g_x + (size_t)(row + 8) * 128 + col) = make_float2(v2, v3);
            }
        }
        return;
    }

    // epilogue B (fused LN path): stage relu'd floats in sFin, then warp-per-row LN + scores
    __syncthreads();   // all warps done reading sA/sW before float overlay
    #pragma unroll
    for (int mt = 0; mt < 4; mt++) {
        #pragma unroll
        for (int nt = 0; nt < 4; nt++) {
            int row = wm + mt * 16 + gq;
            int col = wn + nt * 8 + 2 * tq;
            float b0 = B2[col], b1 = B2[col + 1];
            sFin[row * 132 + col]           = fmaxf(acc[mt][nt][0] + b0, 0.0f);
            sFin[row * 132 + col + 1]       = fmaxf(acc[mt][nt][1] + b1, 0.0f);
            sFin[(row + 8) * 132 + col]     = fmaxf(acc[mt][nt][2] + b0, 0.0f);
            sFin[(row + 8) * 132 + col + 1] = fmaxf(acc[mt][nt][3] + b1, 0.0f);
        }
    }
    __syncthreads();

    float4 gm = reinterpret_cast<const float4*>(gamma)[lane];
    float4 bt = reinterpret_cast<const float4*>(beta)[lane];
    float4 aw0 = reinterpret_cast<const float4*>(aw)[lane];
    float4 aw1 = reinterpret_cast<const float4*>(aw + DD)[lane];

    for (int r = wid * 16; r < wid * 16 + 16; r++) {
        int gr = m0 + r;
        if (gr >= M) break;
        float4 v = *reinterpret_cast<float4*>(&sFin[r * 132 + lane * 4]);

        float s = v.x + v.y + v.z + v.w;
        #pragma unroll
        for (int o = 16; o; o >>= 1) s += __shfl_xor_sync(0xffffffffu, s, o);
        float mu = s * (1.0f / 128.0f);

        float dx = v.x - mu, dy = v.y - mu, dz = v.z - mu, dw = v.w - mu;
        float q = dx * dx + dy * dy + dz * dz + dw * dw;
        #pragma unroll
        for (int o = 16; o; o >>= 1) q += __shfl_xor_sync(0xffffffffu, q, o);
        float rs = rsqrtf(q * (1.0f / 128.0f) + LN_EPS);

        float4 xl;
        xl.x = dx * rs * gm.x + bt.x;
        xl.y = dy * rs * gm.y + bt.y;
        xl.z = dz * rs * gm.z + bt.z;
        xl.w = dw * rs * gm.w + bt.w;
        reinterpret_cast<float4*>(g_xln + (size_t)gr * DD)[lane] = xl;

        float sd = xl.x * aw0.x + xl.y * aw0.y + xl.z * aw0.z + xl.w * aw0.w;
        float ss = xl.x * aw1.x + xl.y * aw1.y + xl.z * aw1.z + xl.w * aw1.w;
        #pragma unroll
        for (int o = 16; o; o >>= 1) {
            sd += __shfl_xor_sync(0xffffffffu, sd, o);
            ss += __shfl_xor_sync(0xffffffffu, ss, o);
        }
        if (lane == 0) { g_sdst[gr] = sd; g_ssrc[gr] = ss; }
    }
}

// ---------------- fused pool + head: one block per graph, binary search boundaries ----------------
__global__ void k_poolhead(const int* __restrict__ batch,
                           const float* __restrict__ wh1, const float* __restrict__ bh1,
                           const float* __restrict__ wh2, const float* __restrict__ bh2,
                           float* __restrict__ out) {
    __shared__ float sg[128];
    __shared__ float sh[64];
    int g = blockIdx.x;
    int t = threadIdx.x;

    int a = 0, b = NN;
    while (a < b) { int m = (a + b) >> 1; if (batch[m] < g) a = m + 1; else b = m; }
    int lo = a;
    b = NN;
    while (a < b) { int m = (a + b) >> 1; if (batch[m] < g + 1) a = m + 1; else b = m; }
    int hi = a;

    float acc0 = 0.f, acc1 = 0.f, acc2 = 0.f, acc3 = 0.f;
    int n = lo;
    for (; n + 3 < hi; n += 4) {
        acc0 += g_x[(size_t)n * DD + t];
        acc1 += g_x[(size_t)(n + 1) * DD + t];
        acc2 += g_x[(size_t)(n + 2) * DD + t];
        acc3 += g_x[(size_t)(n + 3) * DD + t];
    }
    for (; n < hi; n++) acc0 += g_x[(size_t)n * DD + t];

    float cnt = fmaxf((float)(hi - lo), 1.0f);
    sg[t] = ((acc0 + acc1) + (acc2 + acc3)) / cnt;
    __syncthreads();

    if (t < 64) {
        float h = bh1[t];
        #pragma unroll 8
        for (int k = 0; k < 128; k++) h += sg[k] * wh1[k * 64 + t];
        sh[t] = fmaxf(h, 0.0f);
    }
    __syncthreads();
    if (t < 2) {
        float o = bh2[t];
        for (int k = 0; k < 64; k++) o += sh[k] * wh2[k * 2 + t];
        out[g * 2 + t] = o;
    }
}

// ---------------- launch ----------------
extern "C" void kernel_launch(void* const* d_in, const int* in_sizes, int n_in,
                              void* d_out, int out_size) {
    const int*   node_ids = (const int*)d_in[0];
    const int*   edge_idx = (const int*)d_in[1];   // [2, E]
    const float* edge_w   = (const float*)d_in[2];
    const int*   batch    = (const int*)d_in[3];
    const float* emb      = (const float*)d_in[4];
    const float* ln_g     = (const float*)d_in[5];
    const float* ln_b     = (const float*)d_in[6];
    const float* att_w    = (const float*)d_in[7];
    const float* w1       = (const float*)d_in[8];
    const float* b1       = (const float*)d_in[9];
    const float* w2       = (const float*)d_in[10];
    const float* b2       = (const float*)d_in[11];
    const float* epsp     = (const float*)d_in[12];
    const float* wh1      = (const float*)d_in[13];
    const float* bh1      = (const float*)d_in[14];
    const float* wh2      = (const float*)d_in[15];
    const float* bh2      = (const float*)d_in[16];
    float* out = (float*)d_out;

    const int* srcp = edge_idx;
    const int* dstp = edge_idx + EE;

    cudaFuncSetAttribute(k_mlp, cudaFuncAttributeMaxDynamicSharedMemorySize, SMEM_BYTES);

    // zero scratch via memset nodes (not kernel launches)
    void *p_deg, *p_total;
    cudaGetSymbolAddress(&p_deg, g_deg);
    cudaGetSymbolAddress(&p_total, g_total);
    cudaMemsetAsync(p_deg, 0, NN * sizeof(int));
    cudaMemsetAsync(p_total, 0, sizeof(int));

    int small_blocks = NN / 2;               // 25000 (lnhist & agg: 2 warps per block)
    int mlp_blocks   = (NN + 127) / 128;     // 391

    k_lnhist<<<small_blocks, 64>>>(emb, node_ids, ln_g, ln_b, att_w, dstp);
    k_alloc<<<196, 256>>>();
    k_scatter<<<(EE + 255) / 256, 256>>>(srcp, dstp, edge_w);
    // slot 3 for ncu: k_agg layer 0
    k_agg<<<small_blocks, 64>>>(epsp, 0);
    k_mlp<<<mlp_blocks, 256, SMEM_BYTES>>>(w1, b1, w2, b2, NN, /*do_ln=*/1,
                                           ln_g + DD, ln_b + DD, att_w + 2 * DD);
    k_agg<<<small_blocks, 64>>>(epsp, 1);
    k_mlp<<<mlp_blocks, 256, SMEM_BYTES>>>(w1 + DD * DD, b1 + DD, w2 + DD * DD, b2 + DD, NN,
                                           /*do_ln=*/0, nullptr, nullptr, nullptr);

    k_poolhead<<<GG, 128>>>(batch, wh1, bh1, wh2, bh2, out);
}